// round 15
// baseline (speedup 1.0000x reference)
#include <cuda_runtime.h>
#include <cuda_bf16.h>
#include <cstdint>

// ---------------------------------------------------------------------------
// GraphSAGE 3-layer, fp32. N=50000, E=600000, 128->128->128->40.
//   Layers 1,2: mma.sync bf16-split GEMM, BM=64/BN=128 tiles, 2 blocks/SM
//   Layer 3:    FFMA2 GEMM (proven R2 form)
//   Aggregation: fused CSR gather+combine, 8-way MLP (proven R14)
//   CSR build: vectorized (proven R14)
// tcgen05 unavailable (compute_103 PTX target). Launch #4 = gemm128_mma.
// ---------------------------------------------------------------------------

#define MAXN 50000
#define MAXE 600000

static __device__ float          g_TS [MAXN * 256];
static __device__ float          g_H  [MAXN * 128];
static __device__ float          g_rdeg[MAXN];
static __device__ int            g_degi[MAXN];
static __device__ int            g_off [MAXN + 1];
static __device__ int            g_cur [MAXN];
static __device__ int            g_esrc[MAXE];
static __device__ int            g_bsum[256];
static __device__ unsigned short g_Bh[2][256 * 128];
static __device__ unsigned short g_Bl[2][256 * 128];

__device__ __forceinline__ unsigned long long pack2(float x) {
    unsigned long long r;
    asm("mov.b64 %0, {%1, %1};" : "=l"(r) : "f"(x));
    return r;
}
__device__ __forceinline__ void ffma2(unsigned long long& d,
                                      unsigned long long a,
                                      unsigned long long b) {
    asm("fma.rn.f32x2 %0, %1, %2, %0;" : "+l"(d) : "l"(a), "l"(b));
}
union U2F2 { unsigned long long u; float2 f; };

__device__ __forceinline__ uint32_t smem_u32(const void* p) {
    uint32_t a;
    asm("{ .reg .u64 t; cvta.to.shared.u64 t, %1; cvt.u32.u64 %0, t; }"
        : "=r"(a) : "l"(p));
    return a;
}
__device__ __forceinline__ unsigned pbf2(float x, float y) {
    unsigned short ux = __bfloat16_as_ushort(__float2bfloat16(x));
    unsigned short uy = __bfloat16_as_ushort(__float2bfloat16(y));
    return (unsigned)ux | ((unsigned)uy << 16);
}
__device__ __forceinline__ void ldsm_x4(uint32_t* d, uint32_t addr) {
    asm volatile("ldmatrix.sync.aligned.m8n8.x4.shared.b16 {%0,%1,%2,%3}, [%4];"
                 : "=r"(d[0]), "=r"(d[1]), "=r"(d[2]), "=r"(d[3]) : "r"(addr));
}
__device__ __forceinline__ void mma_bf16(float* c, const uint32_t* a, const uint32_t* b) {
    asm volatile(
        "mma.sync.aligned.m16n8k16.row.col.f32.bf16.bf16.f32 "
        "{%0,%1,%2,%3}, {%4,%5,%6,%7}, {%8,%9}, {%0,%1,%2,%3};"
        : "+f"(c[0]), "+f"(c[1]), "+f"(c[2]), "+f"(c[3])
        : "r"(a[0]), "r"(a[1]), "r"(a[2]), "r"(a[3]), "r"(b[0]), "r"(b[1]));
}

// ---------------------------------------------------------------------------
// Weight prep (proven R13)
// ---------------------------------------------------------------------------
__global__ void w_prep(const float* __restrict__ Wn, const float* __restrict__ Ws,
                       unsigned short* __restrict__ bh, unsigned short* __restrict__ bl) {
    int i = blockIdx.x * 256 + threadIdx.x;
    if (i >= 256 * 64) return;
    int n = i >> 6;
    int kp = (i & 63) * 2;
    float w0, w1;
    if (n < 128) { w0 = Wn[kp * 128 + n]; w1 = Wn[(kp + 1) * 128 + n]; }
    else         { w0 = Ws[kp * 128 + n - 128]; w1 = Ws[(kp + 1) * 128 + n - 128]; }
    __nv_bfloat16 h0 = __float2bfloat16(w0), h1 = __float2bfloat16(w1);
    *reinterpret_cast<unsigned*>(bh + n * 128 + kp) =
        (unsigned)__bfloat16_as_ushort(h0) | ((unsigned)__bfloat16_as_ushort(h1) << 16);
    *reinterpret_cast<unsigned*>(bl + n * 128 + kp) =
        pbf2(w0 - __bfloat162float(h0), w1 - __bfloat162float(h1));
}

// ---------------------------------------------------------------------------
// mma.sync GEMM: BM=64 rows (blockIdx.x), BN=128 cols (blockIdx.y half).
// 512 threads, 16 warps, warp tile 16x32. 2 blocks/SM (102KB smem, <=64 regs).
// ---------------------------------------------------------------------------
#define BSTR 136
#define OFF_AHI 0
#define OFF_ALO 17408
#define OFF_BTH 34816
#define OFF_BTL 69632
#define SMEM_MMA 104448

__global__ void __launch_bounds__(512, 2)
gemm128_mma(const float* __restrict__ A,
            const unsigned short* __restrict__ Bhi,
            const unsigned short* __restrict__ Blo,
            float* __restrict__ out, int M) {
    extern __shared__ char smc[];
    unsigned short* Ahi = reinterpret_cast<unsigned short*>(smc + OFF_AHI);
    unsigned short* Alo = reinterpret_cast<unsigned short*>(smc + OFF_ALO);
    unsigned short* Bth = reinterpret_cast<unsigned short*>(smc + OFF_BTH);
    unsigned short* Btl = reinterpret_cast<unsigned short*>(smc + OFF_BTL);

    const int tid = threadIdx.x;
    const int lane = tid & 31;
    const int w = tid >> 5;
    const int row0 = blockIdx.x * 64;
    const int nbase = blockIdx.y * 128;

    // stage A (64 rows, fp32 -> hi/lo bf16)
    for (int i = tid; i < 64 * 32; i += 512) {
        int r = i >> 5;
        int g = i & 31;
        int gr = row0 + r;
        if (gr >= M) gr = M - 1;
        float4 a = *reinterpret_cast<const float4*>(A + (size_t)gr * 128 + g * 4);
        __nv_bfloat16 hx = __float2bfloat16(a.x), hy = __float2bfloat16(a.y);
        __nv_bfloat16 hz = __float2bfloat16(a.z), hw = __float2bfloat16(a.w);
        uint2 hi, lo;
        hi.x = (unsigned)__bfloat16_as_ushort(hx) | ((unsigned)__bfloat16_as_ushort(hy) << 16);
        hi.y = (unsigned)__bfloat16_as_ushort(hz) | ((unsigned)__bfloat16_as_ushort(hw) << 16);
        lo.x = pbf2(a.x - __bfloat162float(hx), a.y - __bfloat162float(hy));
        lo.y = pbf2(a.z - __bfloat162float(hz), a.w - __bfloat162float(hw));
        *reinterpret_cast<uint2*>(Ahi + r * BSTR + g * 4) = hi;
        *reinterpret_cast<uint2*>(Alo + r * BSTR + g * 4) = lo;
    }
    // stage this block's B half (128 n-rows)
    for (int i = tid; i < 128 * 32; i += 512) {
        int n = i >> 5;
        int g = i & 31;
        uint2 h = *reinterpret_cast<const uint2*>(Bhi + (nbase + n) * 128 + g * 4);
        uint2 l = *reinterpret_cast<const uint2*>(Blo + (nbase + n) * 128 + g * 4);
        *reinterpret_cast<uint2*>(Bth + n * BSTR + g * 4) = h;
        *reinterpret_cast<uint2*>(Btl + n * BSTR + g * 4) = l;
    }
    __syncthreads();

    const int wm = w & 3;        // 16-row group (0..3)
    const int wn = w >> 2;       // 32-col group (0..3)
    const int mat = lane >> 3;
    const int rim = lane & 7;

    float acc[4][4];
#pragma unroll
    for (int nt = 0; nt < 4; nt++)
#pragma unroll
        for (int q = 0; q < 4; q++) acc[nt][q] = 0.f;

    const int a_r_base = wm * 16 + (mat & 1) * 8 + rim;
    const int a_k_off = (mat >> 1) * 8;
    const int b_n_base = wn * 32 + (mat >> 1) * 8 + rim;
    const int b_k_off = (mat & 1) * 8;

#pragma unroll
    for (int term = 0; term < 3; term++) {
        const unsigned short* As = (term == 1) ? Alo : Ahi;
        const unsigned short* Bs = (term == 2) ? Btl : Bth;
#pragma unroll
        for (int ks = 0; ks < 8; ks++) {
            const int k0 = ks * 16;
            uint32_t afr[4];
            ldsm_x4(afr, smem_u32(As + a_r_base * BSTR + k0 + a_k_off));
#pragma unroll
            for (int np = 0; np < 2; np++) {
                uint32_t bfr[4];
                ldsm_x4(bfr, smem_u32(Bs + (b_n_base + np * 16) * BSTR + k0 + b_k_off));
                mma_bf16(acc[2 * np],     afr, bfr);
                mma_bf16(acc[2 * np + 1], afr, bfr + 2);
            }
        }
    }

    const int gid = lane >> 2;
    const int tig = lane & 3;
#pragma unroll
    for (int half = 0; half < 2; half++) {
        int r = row0 + wm * 16 + half * 8 + gid;
        if (r < M) {
            float* o = out + (size_t)r * 256 + nbase + wn * 32 + tig * 2;
#pragma unroll
            for (int nt = 0; nt < 4; nt++) {
                float2 v = make_float2(acc[nt][2 * half], acc[nt][2 * half + 1]);
                *reinterpret_cast<float2*>(o + nt * 8) = v;
            }
        }
    }
}

// ---------------------------------------------------------------------------
// CSR build — vectorized (proven R14)
// ---------------------------------------------------------------------------
__global__ void zero_i(int* p, int n) {
    int i = blockIdx.x * blockDim.x + threadIdx.x;
    if (i < n) p[i] = 0;
}
__global__ void count_deg4(const int* __restrict__ dst, int E) {
    int i = blockIdx.x * blockDim.x + threadIdx.x;
    int e0 = i * 4;
    if (e0 + 3 < E) {
        int4 d = *reinterpret_cast<const int4*>(dst + e0);
        atomicAdd(&g_degi[d.x], 1);
        atomicAdd(&g_degi[d.y], 1);
        atomicAdd(&g_degi[d.z], 1);
        atomicAdd(&g_degi[d.w], 1);
    } else {
        for (int e = e0; e < E; ++e) atomicAdd(&g_degi[dst[e]], 1);
    }
}
__global__ void scan_block(const int* __restrict__ in, int* __restrict__ out,
                           int* bsum, int n) {
    int i = blockIdx.x * 256 + threadIdx.x;
    int lane = threadIdx.x & 31, w = threadIdx.x >> 5;
    int v = (i < n) ? in[i] : 0;
    int incl = v;
#pragma unroll
    for (int d = 1; d < 32; d <<= 1) {
        int t = __shfl_up_sync(0xffffffffu, incl, d);
        if (lane >= d) incl += t;
    }
    __shared__ int ws[8];
    if (lane == 31) ws[w] = incl;
    __syncthreads();
    if (threadIdx.x < 8) {
        int x = ws[threadIdx.x];
        int in2 = x;
#pragma unroll
        for (int d = 1; d < 8; d <<= 1) {
            int t = __shfl_up_sync(0xffu, in2, d);
            if (threadIdx.x >= (unsigned)d) in2 += t;
        }
        ws[threadIdx.x] = in2 - x;
        if (threadIdx.x == 7 && bsum) bsum[blockIdx.x] = in2;
    }
    __syncthreads();
    if (i < n) out[i] = ws[w] + incl - v;
}
__global__ void add_off(int M, int E) {
    int i = blockIdx.x * blockDim.x + threadIdx.x;
    if (i < M) {
        int o = g_off[i] + g_bsum[i >> 8];
        g_off[i] = o;
        g_cur[i] = o;
        g_rdeg[i] = 1.0f / fmaxf((float)g_degi[i], 1.0f);
    } else if (i == M) {
        g_off[M] = E;
    }
}
__global__ void scatter_edges4(const int* __restrict__ src,
                               const int* __restrict__ dst, int E) {
    int i = blockIdx.x * blockDim.x + threadIdx.x;
    int e0 = i * 4;
    if (e0 + 3 < E) {
        int4 d = *reinterpret_cast<const int4*>(dst + e0);
        int4 s = *reinterpret_cast<const int4*>(src + e0);
        g_esrc[atomicAdd(&g_cur[d.x], 1)] = s.x;
        g_esrc[atomicAdd(&g_cur[d.y], 1)] = s.y;
        g_esrc[atomicAdd(&g_cur[d.z], 1)] = s.z;
        g_esrc[atomicAdd(&g_cur[d.w], 1)] = s.w;
    } else {
        for (int e = e0; e < E; ++e)
            g_esrc[atomicAdd(&g_cur[dst[e]], 1)] = src[e];
    }
}

// ---------------------------------------------------------------------------
// FFMA2 GEMM for layer 3 (proven R2 form)
// ---------------------------------------------------------------------------
template <int DOUT, int CT, int RT, int TM, int TNP>
__global__ void __launch_bounds__(CT * RT, 1)
gemm_fused(const float* __restrict__ A,
           const float* __restrict__ Wn,
           const float* __restrict__ Ws,
           float* __restrict__ out, int M) {
    constexpr int NOUT = 2 * DOUT;
    constexpr int BM = RT * TM;
    constexpr int NT = CT * RT;
    constexpr int ASTR = 132;

    extern __shared__ float smf[];
    float* Wsh = smf;
    float* Ash = smf + 128 * NOUT;

    const int tid = threadIdx.x;
    const int row0 = blockIdx.x * BM;

    for (int i = tid; i < 128 * (DOUT / 4); i += NT) {
        int k = i / (DOUT / 4);
        int c = (i % (DOUT / 4)) * 4;
        float4 wn = *reinterpret_cast<const float4*>(Wn + k * DOUT + c);
        float4 ws = *reinterpret_cast<const float4*>(Ws + k * DOUT + c);
        *reinterpret_cast<float4*>(Wsh + k * NOUT + c) = wn;
        *reinterpret_cast<float4*>(Wsh + k * NOUT + DOUT + c) = ws;
    }
    for (int i = tid; i < BM * 32; i += NT) {
        int r = i / 32;
        int kc = (i % 32) * 4;
        int gr = row0 + r;
        if (gr >= M) gr = M - 1;
        float4 a = *reinterpret_cast<const float4*>(A + (size_t)gr * 128 + kc);
        *reinterpret_cast<float4*>(Ash + r * ASTR + kc) = a;
    }
    __syncthreads();

    const int ct = tid % CT;
    const int rt = tid / CT;
    const int colbase = ct * (TNP * 2);
    const float* arow = Ash + rt * TM * ASTR;

    unsigned long long acc[TM][TNP];
#pragma unroll
    for (int i = 0; i < TM; i++)
#pragma unroll
        for (int p = 0; p < TNP; p++) acc[i][p] = 0ull;

#pragma unroll 4
    for (int k = 0; k < 128; ++k) {
        unsigned long long w[TNP];
#pragma unroll
        for (int p = 0; p < TNP; p++)
            w[p] = *reinterpret_cast<const unsigned long long*>(
                Wsh + k * NOUT + colbase + 2 * p);
#pragma unroll
        for (int i = 0; i < TM; i++) {
            unsigned long long aa = pack2(arow[i * ASTR + k]);
#pragma unroll
            for (int p = 0; p < TNP; p++) ffma2(acc[i][p], aa, w[p]);
        }
    }

#pragma unroll
    for (int i = 0; i < TM; i++) {
        int gr = row0 + rt * TM + i;
        if (gr < M) {
            float* o = out + (size_t)gr * NOUT + colbase;
#pragma unroll
            for (int p = 0; p < TNP; p += 2) {
                U2F2 u0, u1;
                u0.u = acc[i][p];
                u1.u = acc[i][p + 1];
                *reinterpret_cast<float4*>(o + 2 * p) =
                    make_float4(u0.f.x, u0.f.y, u1.f.x, u1.f.y);
            }
        }
    }
}

// ---------------------------------------------------------------------------
// Fused CSR aggregate + combine — 8-way MLP (proven R14)
// ---------------------------------------------------------------------------
#define ACC4(d, v) { d.x += v.x; d.y += v.y; d.z += v.z; d.w += v.w; }

template <bool RELU>
__global__ void aggcomb128(const float* __restrict__ TS,
                           const float* __restrict__ b,
                           float* __restrict__ out, int M) {
    int n = blockIdx.x * 8 + (threadIdx.x >> 5);
    if (n >= M) return;
    int lane = threadIdx.x & 31;
    int beg = g_off[n], end = g_off[n + 1];

    float4 a0 = make_float4(0.f, 0.f, 0.f, 0.f);
    float4 a1 = make_float4(0.f, 0.f, 0.f, 0.f);
    float4 a2 = make_float4(0.f, 0.f, 0.f, 0.f);
    float4 a3 = make_float4(0.f, 0.f, 0.f, 0.f);

    for (int j0 = beg; j0 < end; j0 += 32) {
        int cnt = min(32, end - j0);
        int s = (lane < cnt) ? g_esrc[j0 + lane] : 0;
        int t = 0;
        for (; t + 7 < cnt; t += 8) {
            int s0 = __shfl_sync(0xffffffffu, s, t);
            int s1 = __shfl_sync(0xffffffffu, s, t + 1);
            int s2 = __shfl_sync(0xffffffffu, s, t + 2);
            int s3 = __shfl_sync(0xffffffffu, s, t + 3);
            int s4 = __shfl_sync(0xffffffffu, s, t + 4);
            int s5 = __shfl_sync(0xffffffffu, s, t + 5);
            int s6 = __shfl_sync(0xffffffffu, s, t + 6);
            int s7 = __shfl_sync(0xffffffffu, s, t + 7);
            float4 v0 = *reinterpret_cast<const float4*>(TS + (size_t)s0 * 256 + lane * 4);
            float4 v1 = *reinterpret_cast<const float4*>(TS + (size_t)s1 * 256 + lane * 4);
            float4 v2 = *reinterpret_cast<const float4*>(TS + (size_t)s2 * 256 + lane * 4);
            float4 v3 = *reinterpret_cast<const float4*>(TS + (size_t)s3 * 256 + lane * 4);
            float4 v4 = *reinterpret_cast<const float4*>(TS + (size_t)s4 * 256 + lane * 4);
            float4 v5 = *reinterpret_cast<const float4*>(TS + (size_t)s5 * 256 + lane * 4);
            float4 v6 = *reinterpret_cast<const float4*>(TS + (size_t)s6 * 256 + lane * 4);
            float4 v7 = *reinterpret_cast<const float4*>(TS + (size_t)s7 * 256 + lane * 4);
            ACC4(a0, v0) ACC4(a1, v1) ACC4(a2, v2) ACC4(a3, v3)
            ACC4(a0, v4) ACC4(a1, v5) ACC4(a2, v6) ACC4(a3, v7)
        }
        for (; t + 3 < cnt; t += 4) {
            int s0 = __shfl_sync(0xffffffffu, s, t);
            int s1 = __shfl_sync(0xffffffffu, s, t + 1);
            int s2 = __shfl_sync(0xffffffffu, s, t + 2);
            int s3 = __shfl_sync(0xffffffffu, s, t + 3);
            float4 v0 = *reinterpret_cast<const float4*>(TS + (size_t)s0 * 256 + lane * 4);
            float4 v1 = *reinterpret_cast<const float4*>(TS + (size_t)s1 * 256 + lane * 4);
            float4 v2 = *reinterpret_cast<const float4*>(TS + (size_t)s2 * 256 + lane * 4);
            float4 v3 = *reinterpret_cast<const float4*>(TS + (size_t)s3 * 256 + lane * 4);
            ACC4(a0, v0) ACC4(a1, v1) ACC4(a2, v2) ACC4(a3, v3)
        }
        for (; t < cnt; ++t) {
            int s0 = __shfl_sync(0xffffffffu, s, t);
            float4 v0 = *reinterpret_cast<const float4*>(TS + (size_t)s0 * 256 + lane * 4);
            ACC4(a0, v0)
        }
    }
    float r = g_rdeg[n];
    float4 sf = *reinterpret_cast<const float4*>(TS + (size_t)n * 256 + 128 + lane * 4);
    float4 bb = *reinterpret_cast<const float4*>(b + lane * 4);
    float4 v;
    v.x = sf.x + (a0.x + a1.x + a2.x + a3.x) * r + bb.x;
    v.y = sf.y + (a0.y + a1.y + a2.y + a3.y) * r + bb.y;
    v.z = sf.z + (a0.z + a1.z + a2.z + a3.z) * r + bb.z;
    v.w = sf.w + (a0.w + a1.w + a2.w + a3.w) * r + bb.w;
    if (RELU) {
        v.x = fmaxf(v.x, 0.f); v.y = fmaxf(v.y, 0.f);
        v.z = fmaxf(v.z, 0.f); v.w = fmaxf(v.w, 0.f);
    }
    *reinterpret_cast<float4*>(out + (size_t)n * 128 + lane * 4) = v;
}

__global__ void aggcomb40(const float* __restrict__ TS,
                          const float* __restrict__ b,
                          float* __restrict__ out, int M) {
    int n = blockIdx.x * 8 + (threadIdx.x >> 5);
    if (n >= M) return;
    int lane = threadIdx.x & 31;
    int beg = g_off[n], end = g_off[n + 1];
    bool act = lane < 10;
    int laneo = act ? lane : 0;

    float4 a0 = make_float4(0.f, 0.f, 0.f, 0.f);
    float4 a1 = make_float4(0.f, 0.f, 0.f, 0.f);
    float4 a2 = make_float4(0.f, 0.f, 0.f, 0.f);
    float4 a3 = make_float4(0.f, 0.f, 0.f, 0.f);

    for (int j0 = beg; j0 < end; j0 += 32) {
        int cnt = min(32, end - j0);
        int s = (lane < cnt) ? g_esrc[j0 + lane] : 0;
        int t = 0;
        for (; t + 7 < cnt; t += 8) {
            int s0 = __shfl_sync(0xffffffffu, s, t);
            int s1 = __shfl_sync(0xffffffffu, s, t + 1);
            int s2 = __shfl_sync(0xffffffffu, s, t + 2);
            int s3 = __shfl_sync(0xffffffffu, s, t + 3);
            int s4 = __shfl_sync(0xffffffffu, s, t + 4);
            int s5 = __shfl_sync(0xffffffffu, s, t + 5);
            int s6 = __shfl_sync(0xffffffffu, s, t + 6);
            int s7 = __shfl_sync(0xffffffffu, s, t + 7);
            float4 v0 = *reinterpret_cast<const float4*>(TS + (size_t)s0 * 80 + laneo * 4);
            float4 v1 = *reinterpret_cast<const float4*>(TS + (size_t)s1 * 80 + laneo * 4);
            float4 v2 = *reinterpret_cast<const float4*>(TS + (size_t)s2 * 80 + laneo * 4);
            float4 v3 = *reinterpret_cast<const float4*>(TS + (size_t)s3 * 80 + laneo * 4);
            float4 v4 = *reinterpret_cast<const float4*>(TS + (size_t)s4 * 80 + laneo * 4);
            float4 v5 = *reinterpret_cast<const float4*>(TS + (size_t)s5 * 80 + laneo * 4);
            float4 v6 = *reinterpret_cast<const float4*>(TS + (size_t)s6 * 80 + laneo * 4);
            float4 v7 = *reinterpret_cast<const float4*>(TS + (size_t)s7 * 80 + laneo * 4);
            ACC4(a0, v0) ACC4(a1, v1) ACC4(a2, v2) ACC4(a3, v3)
            ACC4(a0, v4) ACC4(a1, v5) ACC4(a2, v6) ACC4(a3, v7)
        }
        for (; t + 3 < cnt; t += 4) {
            int s0 = __shfl_sync(0xffffffffu, s, t);
            int s1 = __shfl_sync(0xffffffffu, s, t + 1);
            int s2 = __shfl_sync(0xffffffffu, s, t + 2);
            int s3 = __shfl_sync(0xffffffffu, s, t + 3);
            float4 v0 = *reinterpret_cast<const float4*>(TS + (size_t)s0 * 80 + laneo * 4);
            float4 v1 = *reinterpret_cast<const float4*>(TS + (size_t)s1 * 80 + laneo * 4);
            float4 v2 = *reinterpret_cast<const float4*>(TS + (size_t)s2 * 80 + laneo * 4);
            float4 v3 = *reinterpret_cast<const float4*>(TS + (size_t)s3 * 80 + laneo * 4);
            ACC4(a0, v0) ACC4(a1, v1) ACC4(a2, v2) ACC4(a3, v3)
        }
        for (; t < cnt; ++t) {
            int s0 = __shfl_sync(0xffffffffu, s, t);
            float4 v0 = *reinterpret_cast<const float4*>(TS + (size_t)s0 * 80 + laneo * 4);
            ACC4(a0, v0)
        }
    }
    if (act) {
        float r = g_rdeg[n];
        float4 sf = *reinterpret_cast<const float4*>(TS + (size_t)n * 80 + 40 + lane * 4);
        float4 bb = *reinterpret_cast<const float4*>(b + lane * 4);
        float4 v;
        v.x = sf.x + (a0.x + a1.x + a2.x + a3.x) * r + bb.x;
        v.y = sf.y + (a0.y + a1.y + a2.y + a3.y) * r + bb.y;
        v.z = sf.z + (a0.z + a1.z + a2.z + a3.z) * r + bb.z;
        v.w = sf.w + (a0.w + a1.w + a2.w + a3.w) * r + bb.w;
        *reinterpret_cast<float4*>(out + (size_t)n * 40 + lane * 4) = v;
    }
}

// ---------------------------------------------------------------------------
// launch
// ---------------------------------------------------------------------------
static inline int cdiv(int a, int b) { return (a + b - 1) / b; }

extern "C" void kernel_launch(void* const* d_in, const int* in_sizes, int n_in,
                              void* d_out, int out_size) {
    const float* feat = (const float*)d_in[0];
    const int*   src  = (const int*)d_in[1];
    const int*   dst  = (const int*)d_in[2];
    const float* wS0 = (const float*)d_in[3];
    const float* wN0 = (const float*)d_in[4];
    const float* b0  = (const float*)d_in[5];
    const float* wS1 = (const float*)d_in[6];
    const float* wN1 = (const float*)d_in[7];
    const float* b1  = (const float*)d_in[8];
    const float* wS2 = (const float*)d_in[9];
    const float* wN2 = (const float*)d_in[10];
    const float* b2  = (const float*)d_in[11];
    float* out = (float*)d_out;

    const int M = in_sizes[0] / 128;
    const int E = in_sizes[1];

    void *pTS, *pH, *pDegi, *pOff, *pBsum, *pBh, *pBl;
    cudaGetSymbolAddress(&pTS, g_TS);
    cudaGetSymbolAddress(&pH, g_H);
    cudaGetSymbolAddress(&pDegi, g_degi);
    cudaGetSymbolAddress(&pOff, g_off);
    cudaGetSymbolAddress(&pBsum, g_bsum);
    cudaGetSymbolAddress(&pBh, g_Bh);
    cudaGetSymbolAddress(&pBl, g_Bl);
    float* TS = (float*)pTS;
    float* H = (float*)pH;
    int* degi = (int*)pDegi;
    int* off = (int*)pOff;
    int* bsum = (int*)pBsum;
    unsigned short* Bh = (unsigned short*)pBh;
    unsigned short* Bl = (unsigned short*)pBl;

    constexpr int SMEM_B = (128 * 80 + 128 * 132) * 4;   // 108544 B
    static bool attr_done = false;
    if (!attr_done) {
        cudaFuncSetAttribute((const void*)gemm128_mma,
                             cudaFuncAttributeMaxDynamicSharedMemorySize, SMEM_MMA);
        cudaFuncSetAttribute((const void*)gemm_fused<40, 10, 32, 4, 4>,
                             cudaFuncAttributeMaxDynamicSharedMemorySize, SMEM_B);
        attr_done = true;
    }

    const dim3 gemm_grid(cdiv(M, 64), 2);
    const int gemm3_blocks = cdiv(M, 128);
    const int nscan = cdiv(M, 256);
    const int node_blocks = cdiv(M, 8);
    const int e4_blocks = cdiv(cdiv(E, 4), 256);

    // launch #4 = gemm128_mma (profiler captures it)
    w_prep<<<64, 256>>>(wN0, wS0, Bh + 0 * 32768, Bl + 0 * 32768);    // 1
    w_prep<<<64, 256>>>(wN1, wS1, Bh + 1 * 32768, Bl + 1 * 32768);    // 2
    zero_i<<<cdiv(M, 256), 256>>>(degi, M);                           // 3
    gemm128_mma<<<gemm_grid, 512, SMEM_MMA>>>(feat, Bh, Bl, TS, M);   // 4 (layer1)

    // CSR build (independent of TS)
    count_deg4<<<e4_blocks, 256>>>(dst, E);                           // 5
    scan_block<<<nscan, 256>>>(degi, off, bsum, M);                   // 6
    scan_block<<<1, 256>>>(bsum, bsum, nullptr, nscan);               // 7
    add_off<<<cdiv(M + 1, 256), 256>>>(M, E);                         // 8
    scatter_edges4<<<e4_blocks, 256>>>(src, dst, E);                  // 9

    // layer 1 aggregate
    aggcomb128<true><<<node_blocks, 256>>>(TS, b0, H, M);             // 10

    // layer 2
    gemm128_mma<<<gemm_grid, 512, SMEM_MMA>>>(H, Bh + 32768, Bl + 32768, TS, M);
    aggcomb128<true><<<node_blocks, 256>>>(TS, b1, H, M);

    // layer 3
    gemm_fused<40, 10, 32, 4, 4><<<gemm3_blocks, 320, SMEM_B>>>(H, wN2, wS2, TS, M);
    aggcomb40<<<node_blocks, 256>>>(TS, b2, out, M);
}

// round 16
// speedup vs baseline: 1.3560x; 1.3560x over previous
#include <cuda_runtime.h>
#include <cuda_bf16.h>
#include <cstdint>

// ---------------------------------------------------------------------------
// GraphSAGE 3-layer, fp32. N=50000, E=600000, 128->128->128->40.
//   Layers 1,2: mma.sync bf16-split GEMM, R14 tile (BM=128,BN=256),
//               FUSED 3-term inner loop (each fragment loaded once)
//   Layer 3:    FFMA2 GEMM (proven R2 form)
//   Aggregation: fused CSR gather+combine, 8-way MLP (proven R14)
//   CSR build: vectorized (proven R14)
// tcgen05 unavailable (compute_103 PTX target). Launch #4 = gemm128_mma.
// ---------------------------------------------------------------------------

#define MAXN 50000
#define MAXE 600000

static __device__ float          g_TS [MAXN * 256];
static __device__ float          g_H  [MAXN * 128];
static __device__ float          g_rdeg[MAXN];
static __device__ int            g_degi[MAXN];
static __device__ int            g_off [MAXN + 1];
static __device__ int            g_cur [MAXN];
static __device__ int            g_esrc[MAXE];
static __device__ int            g_bsum[256];
static __device__ unsigned short g_Bh[2][256 * 128];
static __device__ unsigned short g_Bl[2][256 * 128];

__device__ __forceinline__ unsigned long long pack2(float x) {
    unsigned long long r;
    asm("mov.b64 %0, {%1, %1};" : "=l"(r) : "f"(x));
    return r;
}
__device__ __forceinline__ void ffma2(unsigned long long& d,
                                      unsigned long long a,
                                      unsigned long long b) {
    asm("fma.rn.f32x2 %0, %1, %2, %0;" : "+l"(d) : "l"(a), "l"(b));
}
union U2F2 { unsigned long long u; float2 f; };

__device__ __forceinline__ uint32_t smem_u32(const void* p) {
    uint32_t a;
    asm("{ .reg .u64 t; cvta.to.shared.u64 t, %1; cvt.u32.u64 %0, t; }"
        : "=r"(a) : "l"(p));
    return a;
}
__device__ __forceinline__ unsigned pbf2(float x, float y) {
    unsigned short ux = __bfloat16_as_ushort(__float2bfloat16(x));
    unsigned short uy = __bfloat16_as_ushort(__float2bfloat16(y));
    return (unsigned)ux | ((unsigned)uy << 16);
}
__device__ __forceinline__ void ldsm_x4(uint32_t* d, uint32_t addr) {
    asm volatile("ldmatrix.sync.aligned.m8n8.x4.shared.b16 {%0,%1,%2,%3}, [%4];"
                 : "=r"(d[0]), "=r"(d[1]), "=r"(d[2]), "=r"(d[3]) : "r"(addr));
}
__device__ __forceinline__ void mma_bf16(float* c, const uint32_t* a, const uint32_t* b) {
    asm volatile(
        "mma.sync.aligned.m16n8k16.row.col.f32.bf16.bf16.f32 "
        "{%0,%1,%2,%3}, {%4,%5,%6,%7}, {%8,%9}, {%0,%1,%2,%3};"
        : "+f"(c[0]), "+f"(c[1]), "+f"(c[2]), "+f"(c[3])
        : "r"(a[0]), "r"(a[1]), "r"(a[2]), "r"(a[3]), "r"(b[0]), "r"(b[1]));
}

// ---------------------------------------------------------------------------
// Weight prep (proven R13)
// ---------------------------------------------------------------------------
__global__ void w_prep(const float* __restrict__ Wn, const float* __restrict__ Ws,
                       unsigned short* __restrict__ bh, unsigned short* __restrict__ bl) {
    int i = blockIdx.x * 256 + threadIdx.x;
    if (i >= 256 * 64) return;
    int n = i >> 6;
    int kp = (i & 63) * 2;
    float w0, w1;
    if (n < 128) { w0 = Wn[kp * 128 + n]; w1 = Wn[(kp + 1) * 128 + n]; }
    else         { w0 = Ws[kp * 128 + n - 128]; w1 = Ws[(kp + 1) * 128 + n - 128]; }
    __nv_bfloat16 h0 = __float2bfloat16(w0), h1 = __float2bfloat16(w1);
    *reinterpret_cast<unsigned*>(bh + n * 128 + kp) =
        (unsigned)__bfloat16_as_ushort(h0) | ((unsigned)__bfloat16_as_ushort(h1) << 16);
    *reinterpret_cast<unsigned*>(bl + n * 128 + kp) =
        pbf2(w0 - __bfloat162float(h0), w1 - __bfloat162float(h1));
}

// ---------------------------------------------------------------------------
// mma.sync GEMM: R14 tile (BM=128, BN=256), fused 3-term inner loop.
// 512 threads, 16 warps, warp tile 32x64.
// ---------------------------------------------------------------------------
#define BSTR 136
#define OFF_AHI 0
#define OFF_ALO 34816
#define OFF_BTH 69632
#define OFF_BTL 139264
#define SMEM_MMA 208896

__global__ void __launch_bounds__(512, 1)
gemm128_mma(const float* __restrict__ A,
            const unsigned short* __restrict__ Bhi,
            const unsigned short* __restrict__ Blo,
            float* __restrict__ out, int M) {
    extern __shared__ char smc[];
    unsigned short* Ahi = reinterpret_cast<unsigned short*>(smc + OFF_AHI);
    unsigned short* Alo = reinterpret_cast<unsigned short*>(smc + OFF_ALO);
    unsigned short* Bth = reinterpret_cast<unsigned short*>(smc + OFF_BTH);
    unsigned short* Btl = reinterpret_cast<unsigned short*>(smc + OFF_BTL);

    const int tid = threadIdx.x;
    const int lane = tid & 31;
    const int w = tid >> 5;
    const int row0 = blockIdx.x * 128;

    for (int i = tid; i < 128 * 32; i += 512) {
        int r = i >> 5;
        int g = i & 31;
        int gr = row0 + r;
        if (gr >= M) gr = M - 1;
        float4 a = *reinterpret_cast<const float4*>(A + (size_t)gr * 128 + g * 4);
        __nv_bfloat16 hx = __float2bfloat16(a.x), hy = __float2bfloat16(a.y);
        __nv_bfloat16 hz = __float2bfloat16(a.z), hw = __float2bfloat16(a.w);
        uint2 hi, lo;
        hi.x = (unsigned)__bfloat16_as_ushort(hx) | ((unsigned)__bfloat16_as_ushort(hy) << 16);
        hi.y = (unsigned)__bfloat16_as_ushort(hz) | ((unsigned)__bfloat16_as_ushort(hw) << 16);
        lo.x = pbf2(a.x - __bfloat162float(hx), a.y - __bfloat162float(hy));
        lo.y = pbf2(a.z - __bfloat162float(hz), a.w - __bfloat162float(hw));
        *reinterpret_cast<uint2*>(Ahi + r * BSTR + g * 4) = hi;
        *reinterpret_cast<uint2*>(Alo + r * BSTR + g * 4) = lo;
    }
    for (int i = tid; i < 256 * 32; i += 512) {
        int n = i >> 5;
        int g = i & 31;
        uint2 h = *reinterpret_cast<const uint2*>(Bhi + n * 128 + g * 4);
        uint2 l = *reinterpret_cast<const uint2*>(Blo + n * 128 + g * 4);
        *reinterpret_cast<uint2*>(Bth + n * BSTR + g * 4) = h;
        *reinterpret_cast<uint2*>(Btl + n * BSTR + g * 4) = l;
    }
    __syncthreads();

    const int wm = w & 3;
    const int wn = w >> 2;
    const int mat = lane >> 3;
    const int rim = lane & 7;

    float acc[2][8][4];
#pragma unroll
    for (int mt = 0; mt < 2; mt++)
#pragma unroll
        for (int nt = 0; nt < 8; nt++)
#pragma unroll
            for (int q = 0; q < 4; q++) acc[mt][nt][q] = 0.f;

    const int a_r_base = wm * 32 + (mat & 1) * 8 + rim;
    const int a_k_off = (mat >> 1) * 8;
    const int b_n_base = wn * 64 + (mat >> 1) * 8 + rim;
    const int b_k_off = (mat & 1) * 8;

    // fused 3-term loop: each fragment loaded once per ks
#pragma unroll
    for (int ks = 0; ks < 8; ks++) {
        const int k0 = ks * 16;
        uint32_t ah[2][4], al[2][4];
#pragma unroll
        for (int mt = 0; mt < 2; mt++) {
            int ro = (a_r_base + mt * 16) * BSTR + k0 + a_k_off;
            ldsm_x4(ah[mt], smem_u32(Ahi + ro));
            ldsm_x4(al[mt], smem_u32(Alo + ro));
        }
#pragma unroll
        for (int np = 0; np < 4; np++) {
            uint32_t bh[4], bl[4];
            int no = (b_n_base + np * 16) * BSTR + k0 + b_k_off;
            ldsm_x4(bh, smem_u32(Bth + no));
            ldsm_x4(bl, smem_u32(Btl + no));
#pragma unroll
            for (int mt = 0; mt < 2; mt++) {
                float* c0 = acc[mt][2 * np];
                float* c1 = acc[mt][2 * np + 1];
                mma_bf16(c0, ah[mt], bh);
                mma_bf16(c1, ah[mt], bh + 2);
                mma_bf16(c0, al[mt], bh);
                mma_bf16(c1, al[mt], bh + 2);
                mma_bf16(c0, ah[mt], bl);
                mma_bf16(c1, ah[mt], bl + 2);
            }
        }
    }

    const int gid = lane >> 2;
    const int tig = lane & 3;
#pragma unroll
    for (int mt = 0; mt < 2; mt++) {
#pragma unroll
        for (int half = 0; half < 2; half++) {
            int r = row0 + wm * 32 + mt * 16 + half * 8 + gid;
            if (r < M) {
                float* o = out + (size_t)r * 256 + wn * 64 + tig * 2;
#pragma unroll
                for (int nt = 0; nt < 8; nt++) {
                    float2 v = make_float2(acc[mt][nt][2 * half], acc[mt][nt][2 * half + 1]);
                    *reinterpret_cast<float2*>(o + nt * 8) = v;
                }
            }
        }
    }
}

// ---------------------------------------------------------------------------
// CSR build — vectorized (proven R14)
// ---------------------------------------------------------------------------
__global__ void zero_i(int* p, int n) {
    int i = blockIdx.x * blockDim.x + threadIdx.x;
    if (i < n) p[i] = 0;
}
__global__ void count_deg4(const int* __restrict__ dst, int E) {
    int i = blockIdx.x * blockDim.x + threadIdx.x;
    int e0 = i * 4;
    if (e0 + 3 < E) {
        int4 d = *reinterpret_cast<const int4*>(dst + e0);
        atomicAdd(&g_degi[d.x], 1);
        atomicAdd(&g_degi[d.y], 1);
        atomicAdd(&g_degi[d.z], 1);
        atomicAdd(&g_degi[d.w], 1);
    } else {
        for (int e = e0; e < E; ++e) atomicAdd(&g_degi[dst[e]], 1);
    }
}
__global__ void scan_block(const int* __restrict__ in, int* __restrict__ out,
                           int* bsum, int n) {
    int i = blockIdx.x * 256 + threadIdx.x;
    int lane = threadIdx.x & 31, w = threadIdx.x >> 5;
    int v = (i < n) ? in[i] : 0;
    int incl = v;
#pragma unroll
    for (int d = 1; d < 32; d <<= 1) {
        int t = __shfl_up_sync(0xffffffffu, incl, d);
        if (lane >= d) incl += t;
    }
    __shared__ int ws[8];
    if (lane == 31) ws[w] = incl;
    __syncthreads();
    if (threadIdx.x < 8) {
        int x = ws[threadIdx.x];
        int in2 = x;
#pragma unroll
        for (int d = 1; d < 8; d <<= 1) {
            int t = __shfl_up_sync(0xffu, in2, d);
            if (threadIdx.x >= (unsigned)d) in2 += t;
        }
        ws[threadIdx.x] = in2 - x;
        if (threadIdx.x == 7 && bsum) bsum[blockIdx.x] = in2;
    }
    __syncthreads();
    if (i < n) out[i] = ws[w] + incl - v;
}
__global__ void add_off(int M, int E) {
    int i = blockIdx.x * blockDim.x + threadIdx.x;
    if (i < M) {
        int o = g_off[i] + g_bsum[i >> 8];
        g_off[i] = o;
        g_cur[i] = o;
        g_rdeg[i] = 1.0f / fmaxf((float)g_degi[i], 1.0f);
    } else if (i == M) {
        g_off[M] = E;
    }
}
__global__ void scatter_edges4(const int* __restrict__ src,
                               const int* __restrict__ dst, int E) {
    int i = blockIdx.x * blockDim.x + threadIdx.x;
    int e0 = i * 4;
    if (e0 + 3 < E) {
        int4 d = *reinterpret_cast<const int4*>(dst + e0);
        int4 s = *reinterpret_cast<const int4*>(src + e0);
        g_esrc[atomicAdd(&g_cur[d.x], 1)] = s.x;
        g_esrc[atomicAdd(&g_cur[d.y], 1)] = s.y;
        g_esrc[atomicAdd(&g_cur[d.z], 1)] = s.z;
        g_esrc[atomicAdd(&g_cur[d.w], 1)] = s.w;
    } else {
        for (int e = e0; e < E; ++e)
            g_esrc[atomicAdd(&g_cur[dst[e]], 1)] = src[e];
    }
}

// ---------------------------------------------------------------------------
// FFMA2 GEMM for layer 3 (proven R2 form)
// ---------------------------------------------------------------------------
template <int DOUT, int CT, int RT, int TM, int TNP>
__global__ void __launch_bounds__(CT * RT, 1)
gemm_fused(const float* __restrict__ A,
           const float* __restrict__ Wn,
           const float* __restrict__ Ws,
           float* __restrict__ out, int M) {
    constexpr int NOUT = 2 * DOUT;
    constexpr int BM = RT * TM;
    constexpr int NT = CT * RT;
    constexpr int ASTR = 132;

    extern __shared__ float smf[];
    float* Wsh = smf;
    float* Ash = smf + 128 * NOUT;

    const int tid = threadIdx.x;
    const int row0 = blockIdx.x * BM;

    for (int i = tid; i < 128 * (DOUT / 4); i += NT) {
        int k = i / (DOUT / 4);
        int c = (i % (DOUT / 4)) * 4;
        float4 wn = *reinterpret_cast<const float4*>(Wn + k * DOUT + c);
        float4 ws = *reinterpret_cast<const float4*>(Ws + k * DOUT + c);
        *reinterpret_cast<float4*>(Wsh + k * NOUT + c) = wn;
        *reinterpret_cast<float4*>(Wsh + k * NOUT + DOUT + c) = ws;
    }
    for (int i = tid; i < BM * 32; i += NT) {
        int r = i / 32;
        int kc = (i % 32) * 4;
        int gr = row0 + r;
        if (gr >= M) gr = M - 1;
        float4 a = *reinterpret_cast<const float4*>(A + (size_t)gr * 128 + kc);
        *reinterpret_cast<float4*>(Ash + r * ASTR + kc) = a;
    }
    __syncthreads();

    const int ct = tid % CT;
    const int rt = tid / CT;
    const int colbase = ct * (TNP * 2);
    const float* arow = Ash + rt * TM * ASTR;

    unsigned long long acc[TM][TNP];
#pragma unroll
    for (int i = 0; i < TM; i++)
#pragma unroll
        for (int p = 0; p < TNP; p++) acc[i][p] = 0ull;

#pragma unroll 4
    for (int k = 0; k < 128; ++k) {
        unsigned long long w[TNP];
#pragma unroll
        for (int p = 0; p < TNP; p++)
            w[p] = *reinterpret_cast<const unsigned long long*>(
                Wsh + k * NOUT + colbase + 2 * p);
#pragma unroll
        for (int i = 0; i < TM; i++) {
            unsigned long long aa = pack2(arow[i * ASTR + k]);
#pragma unroll
            for (int p = 0; p < TNP; p++) ffma2(acc[i][p], aa, w[p]);
        }
    }

#pragma unroll
    for (int i = 0; i < TM; i++) {
        int gr = row0 + rt * TM + i;
        if (gr < M) {
            float* o = out + (size_t)gr * NOUT + colbase;
#pragma unroll
            for (int p = 0; p < TNP; p += 2) {
                U2F2 u0, u1;
                u0.u = acc[i][p];
                u1.u = acc[i][p + 1];
                *reinterpret_cast<float4*>(o + 2 * p) =
                    make_float4(u0.f.x, u0.f.y, u1.f.x, u1.f.y);
            }
        }
    }
}

// ---------------------------------------------------------------------------
// Fused CSR aggregate + combine — 8-way MLP (proven R14)
// ---------------------------------------------------------------------------
#define ACC4(d, v) { d.x += v.x; d.y += v.y; d.z += v.z; d.w += v.w; }

template <bool RELU>
__global__ void aggcomb128(const float* __restrict__ TS,
                           const float* __restrict__ b,
                           float* __restrict__ out, int M) {
    int n = blockIdx.x * 8 + (threadIdx.x >> 5);
    if (n >= M) return;
    int lane = threadIdx.x & 31;
    int beg = g_off[n], end = g_off[n + 1];

    float4 a0 = make_float4(0.f, 0.f, 0.f, 0.f);
    float4 a1 = make_float4(0.f, 0.f, 0.f, 0.f);
    float4 a2 = make_float4(0.f, 0.f, 0.f, 0.f);
    float4 a3 = make_float4(0.f, 0.f, 0.f, 0.f);

    for (int j0 = beg; j0 < end; j0 += 32) {
        int cnt = min(32, end - j0);
        int s = (lane < cnt) ? g_esrc[j0 + lane] : 0;
        int t = 0;
        for (; t + 7 < cnt; t += 8) {
            int s0 = __shfl_sync(0xffffffffu, s, t);
            int s1 = __shfl_sync(0xffffffffu, s, t + 1);
            int s2 = __shfl_sync(0xffffffffu, s, t + 2);
            int s3 = __shfl_sync(0xffffffffu, s, t + 3);
            int s4 = __shfl_sync(0xffffffffu, s, t + 4);
            int s5 = __shfl_sync(0xffffffffu, s, t + 5);
            int s6 = __shfl_sync(0xffffffffu, s, t + 6);
            int s7 = __shfl_sync(0xffffffffu, s, t + 7);
            float4 v0 = *reinterpret_cast<const float4*>(TS + (size_t)s0 * 256 + lane * 4);
            float4 v1 = *reinterpret_cast<const float4*>(TS + (size_t)s1 * 256 + lane * 4);
            float4 v2 = *reinterpret_cast<const float4*>(TS + (size_t)s2 * 256 + lane * 4);
            float4 v3 = *reinterpret_cast<const float4*>(TS + (size_t)s3 * 256 + lane * 4);
            float4 v4 = *reinterpret_cast<const float4*>(TS + (size_t)s4 * 256 + lane * 4);
            float4 v5 = *reinterpret_cast<const float4*>(TS + (size_t)s5 * 256 + lane * 4);
            float4 v6 = *reinterpret_cast<const float4*>(TS + (size_t)s6 * 256 + lane * 4);
            float4 v7 = *reinterpret_cast<const float4*>(TS + (size_t)s7 * 256 + lane * 4);
            ACC4(a0, v0) ACC4(a1, v1) ACC4(a2, v2) ACC4(a3, v3)
            ACC4(a0, v4) ACC4(a1, v5) ACC4(a2, v6) ACC4(a3, v7)
        }
        for (; t + 3 < cnt; t += 4) {
            int s0 = __shfl_sync(0xffffffffu, s, t);
            int s1 = __shfl_sync(0xffffffffu, s, t + 1);
            int s2 = __shfl_sync(0xffffffffu, s, t + 2);
            int s3 = __shfl_sync(0xffffffffu, s, t + 3);
            float4 v0 = *reinterpret_cast<const float4*>(TS + (size_t)s0 * 256 + lane * 4);
            float4 v1 = *reinterpret_cast<const float4*>(TS + (size_t)s1 * 256 + lane * 4);
            float4 v2 = *reinterpret_cast<const float4*>(TS + (size_t)s2 * 256 + lane * 4);
            float4 v3 = *reinterpret_cast<const float4*>(TS + (size_t)s3 * 256 + lane * 4);
            ACC4(a0, v0) ACC4(a1, v1) ACC4(a2, v2) ACC4(a3, v3)
        }
        for (; t < cnt; ++t) {
            int s0 = __shfl_sync(0xffffffffu, s, t);
            float4 v0 = *reinterpret_cast<const float4*>(TS + (size_t)s0 * 256 + lane * 4);
            ACC4(a0, v0)
        }
    }
    float r = g_rdeg[n];
    float4 sf = *reinterpret_cast<const float4*>(TS + (size_t)n * 256 + 128 + lane * 4);
    float4 bb = *reinterpret_cast<const float4*>(b + lane * 4);
    float4 v;
    v.x = sf.x + (a0.x + a1.x + a2.x + a3.x) * r + bb.x;
    v.y = sf.y + (a0.y + a1.y + a2.y + a3.y) * r + bb.y;
    v.z = sf.z + (a0.z + a1.z + a2.z + a3.z) * r + bb.z;
    v.w = sf.w + (a0.w + a1.w + a2.w + a3.w) * r + bb.w;
    if (RELU) {
        v.x = fmaxf(v.x, 0.f); v.y = fmaxf(v.y, 0.f);
        v.z = fmaxf(v.z, 0.f); v.w = fmaxf(v.w, 0.f);
    }
    *reinterpret_cast<float4*>(out + (size_t)n * 128 + lane * 4) = v;
}

__global__ void aggcomb40(const float* __restrict__ TS,
                          const float* __restrict__ b,
                          float* __restrict__ out, int M) {
    int n = blockIdx.x * 8 + (threadIdx.x >> 5);
    if (n >= M) return;
    int lane = threadIdx.x & 31;
    int beg = g_off[n], end = g_off[n + 1];
    bool act = lane < 10;
    int laneo = act ? lane : 0;

    float4 a0 = make_float4(0.f, 0.f, 0.f, 0.f);
    float4 a1 = make_float4(0.f, 0.f, 0.f, 0.f);
    float4 a2 = make_float4(0.f, 0.f, 0.f, 0.f);
    float4 a3 = make_float4(0.f, 0.f, 0.f, 0.f);

    for (int j0 = beg; j0 < end; j0 += 32) {
        int cnt = min(32, end - j0);
        int s = (lane < cnt) ? g_esrc[j0 + lane] : 0;
        int t = 0;
        for (; t + 7 < cnt; t += 8) {
            int s0 = __shfl_sync(0xffffffffu, s, t);
            int s1 = __shfl_sync(0xffffffffu, s, t + 1);
            int s2 = __shfl_sync(0xffffffffu, s, t + 2);
            int s3 = __shfl_sync(0xffffffffu, s, t + 3);
            int s4 = __shfl_sync(0xffffffffu, s, t + 4);
            int s5 = __shfl_sync(0xffffffffu, s, t + 5);
            int s6 = __shfl_sync(0xffffffffu, s, t + 6);
            int s7 = __shfl_sync(0xffffffffu, s, t + 7);
            float4 v0 = *reinterpret_cast<const float4*>(TS + (size_t)s0 * 80 + laneo * 4);
            float4 v1 = *reinterpret_cast<const float4*>(TS + (size_t)s1 * 80 + laneo * 4);
            float4 v2 = *reinterpret_cast<const float4*>(TS + (size_t)s2 * 80 + laneo * 4);
            float4 v3 = *reinterpret_cast<const float4*>(TS + (size_t)s3 * 80 + laneo * 4);
            float4 v4 = *reinterpret_cast<const float4*>(TS + (size_t)s4 * 80 + laneo * 4);
            float4 v5 = *reinterpret_cast<const float4*>(TS + (size_t)s5 * 80 + laneo * 4);
            float4 v6 = *reinterpret_cast<const float4*>(TS + (size_t)s6 * 80 + laneo * 4);
            float4 v7 = *reinterpret_cast<const float4*>(TS + (size_t)s7 * 80 + laneo * 4);
            ACC4(a0, v0) ACC4(a1, v1) ACC4(a2, v2) ACC4(a3, v3)
            ACC4(a0, v4) ACC4(a1, v5) ACC4(a2, v6) ACC4(a3, v7)
        }
        for (; t + 3 < cnt; t += 4) {
            int s0 = __shfl_sync(0xffffffffu, s, t);
            int s1 = __shfl_sync(0xffffffffu, s, t + 1);
            int s2 = __shfl_sync(0xffffffffu, s, t + 2);
            int s3 = __shfl_sync(0xffffffffu, s, t + 3);
            float4 v0 = *reinterpret_cast<const float4*>(TS + (size_t)s0 * 80 + laneo * 4);
            float4 v1 = *reinterpret_cast<const float4*>(TS + (size_t)s1 * 80 + laneo * 4);
            float4 v2 = *reinterpret_cast<const float4*>(TS + (size_t)s2 * 80 + laneo * 4);
            float4 v3 = *reinterpret_cast<const float4*>(TS + (size_t)s3 * 80 + laneo * 4);
            ACC4(a0, v0) ACC4(a1, v1) ACC4(a2, v2) ACC4(a3, v3)
        }
        for (; t < cnt; ++t) {
            int s0 = __shfl_sync(0xffffffffu, s, t);
            float4 v0 = *reinterpret_cast<const float4*>(TS + (size_t)s0 * 80 + laneo * 4);
            ACC4(a0, v0)
        }
    }
    if (act) {
        float r = g_rdeg[n];
        float4 sf = *reinterpret_cast<const float4*>(TS + (size_t)n * 80 + 40 + lane * 4);
        float4 bb = *reinterpret_cast<const float4*>(b + lane * 4);
        float4 v;
        v.x = sf.x + (a0.x + a1.x + a2.x + a3.x) * r + bb.x;
        v.y = sf.y + (a0.y + a1.y + a2.y + a3.y) * r + bb.y;
        v.z = sf.z + (a0.z + a1.z + a2.z + a3.z) * r + bb.z;
        v.w = sf.w + (a0.w + a1.w + a2.w + a3.w) * r + bb.w;
        *reinterpret_cast<float4*>(out + (size_t)n * 40 + lane * 4) = v;
    }
}

// ---------------------------------------------------------------------------
// launch
// ---------------------------------------------------------------------------
static inline int cdiv(int a, int b) { return (a + b - 1) / b; }

extern "C" void kernel_launch(void* const* d_in, const int* in_sizes, int n_in,
                              void* d_out, int out_size) {
    const float* feat = (const float*)d_in[0];
    const int*   src  = (const int*)d_in[1];
    const int*   dst  = (const int*)d_in[2];
    const float* wS0 = (const float*)d_in[3];
    const float* wN0 = (const float*)d_in[4];
    const float* b0  = (const float*)d_in[5];
    const float* wS1 = (const float*)d_in[6];
    const float* wN1 = (const float*)d_in[7];
    const float* b1  = (const float*)d_in[8];
    const float* wS2 = (const float*)d_in[9];
    const float* wN2 = (const float*)d_in[10];
    const float* b2  = (const float*)d_in[11];
    float* out = (float*)d_out;

    const int M = in_sizes[0] / 128;
    const int E = in_sizes[1];

    void *pTS, *pH, *pDegi, *pOff, *pBsum, *pBh, *pBl;
    cudaGetSymbolAddress(&pTS, g_TS);
    cudaGetSymbolAddress(&pH, g_H);
    cudaGetSymbolAddress(&pDegi, g_degi);
    cudaGetSymbolAddress(&pOff, g_off);
    cudaGetSymbolAddress(&pBsum, g_bsum);
    cudaGetSymbolAddress(&pBh, g_Bh);
    cudaGetSymbolAddress(&pBl, g_Bl);
    float* TS = (float*)pTS;
    float* H = (float*)pH;
    int* degi = (int*)pDegi;
    int* off = (int*)pOff;
    int* bsum = (int*)pBsum;
    unsigned short* Bh = (unsigned short*)pBh;
    unsigned short* Bl = (unsigned short*)pBl;

    constexpr int SMEM_B = (128 * 80 + 128 * 132) * 4;   // 108544 B
    static bool attr_done = false;
    if (!attr_done) {
        cudaFuncSetAttribute((const void*)gemm128_mma,
                             cudaFuncAttributeMaxDynamicSharedMemorySize, SMEM_MMA);
        cudaFuncSetAttribute((const void*)gemm_fused<40, 10, 32, 4, 4>,
                             cudaFuncAttributeMaxDynamicSharedMemorySize, SMEM_B);
        attr_done = true;
    }

    const int gemm_blocks = cdiv(M, 128);
    const int nscan = cdiv(M, 256);
    const int node_blocks = cdiv(M, 8);
    const int e4_blocks = cdiv(cdiv(E, 4), 256);

    // launch #4 = gemm128_mma (profiler captures it)
    w_prep<<<64, 256>>>(wN0, wS0, Bh + 0 * 32768, Bl + 0 * 32768);    // 1
    w_prep<<<64, 256>>>(wN1, wS1, Bh + 1 * 32768, Bl + 1 * 32768);    // 2
    zero_i<<<cdiv(M, 256), 256>>>(degi, M);                           // 3
    gemm128_mma<<<gemm_blocks, 512, SMEM_MMA>>>(feat, Bh, Bl, TS, M); // 4 (layer1)

    // CSR build (independent of TS)
    count_deg4<<<e4_blocks, 256>>>(dst, E);                           // 5
    scan_block<<<nscan, 256>>>(degi, off, bsum, M);                   // 6
    scan_block<<<1, 256>>>(bsum, bsum, nullptr, nscan);               // 7
    add_off<<<cdiv(M + 1, 256), 256>>>(M, E);                         // 8
    scatter_edges4<<<e4_blocks, 256>>>(src, dst, E);                  // 9

    // layer 1 aggregate
    aggcomb128<true><<<node_blocks, 256>>>(TS, b0, H, M);             // 10

    // layer 2
    gemm128_mma<<<gemm_blocks, 512, SMEM_MMA>>>(H, Bh + 32768, Bl + 32768, TS, M);
    aggcomb128<true><<<node_blocks, 256>>>(TS, b1, H, M);

    // layer 3
    gemm_fused<40, 10, 32, 4, 4><<<gemm_blocks, 320, SMEM_B>>>(H, wN2, wS2, TS, M);
    aggcomb40<<<node_blocks, 256>>>(TS, b2, out, M);
}

// round 17
// speedup vs baseline: 1.5024x; 1.1079x over previous
#include <cuda_runtime.h>
#include <cuda_bf16.h>
#include <cstdint>

// ---------------------------------------------------------------------------
// GraphSAGE 3-layer, fp32. N=50000, E=600000, 128->128->128->40.
//   Layers 1,2: mma.sync bf16-split GEMM, BM=128/BN=256, fused 3-term (R16)
//   Layer 3:    mma.sync bf16-split GEMM, BM=128/BN=96(80 used), fused 3-term
//   Aggregation: fused CSR gather+combine, 8-way MLP (proven R14)
//   CSR build: vectorized (proven R14)
// tcgen05 unavailable (compute_103 PTX target). Launch #4 = gemm128_mma.
// ---------------------------------------------------------------------------

#define MAXN 50000
#define MAXE 600000

static __device__ float          g_TS [MAXN * 256];
static __device__ float          g_H  [MAXN * 128];
static __device__ float          g_rdeg[MAXN];
static __device__ int            g_degi[MAXN];
static __device__ int            g_off [MAXN + 1];
static __device__ int            g_cur [MAXN];
static __device__ int            g_esrc[MAXE];
static __device__ int            g_bsum[256];
static __device__ unsigned short g_Bh[2][256 * 128];
static __device__ unsigned short g_Bl[2][256 * 128];
static __device__ unsigned short g_Bh3[96 * 128];
static __device__ unsigned short g_Bl3[96 * 128];

__device__ __forceinline__ uint32_t smem_u32(const void* p) {
    uint32_t a;
    asm("{ .reg .u64 t; cvta.to.shared.u64 t, %1; cvt.u32.u64 %0, t; }"
        : "=r"(a) : "l"(p));
    return a;
}
__device__ __forceinline__ unsigned pbf2(float x, float y) {
    unsigned short ux = __bfloat16_as_ushort(__float2bfloat16(x));
    unsigned short uy = __bfloat16_as_ushort(__float2bfloat16(y));
    return (unsigned)ux | ((unsigned)uy << 16);
}
__device__ __forceinline__ void ldsm_x4(uint32_t* d, uint32_t addr) {
    asm volatile("ldmatrix.sync.aligned.m8n8.x4.shared.b16 {%0,%1,%2,%3}, [%4];"
                 : "=r"(d[0]), "=r"(d[1]), "=r"(d[2]), "=r"(d[3]) : "r"(addr));
}
__device__ __forceinline__ void mma_bf16(float* c, const uint32_t* a, const uint32_t* b) {
    asm volatile(
        "mma.sync.aligned.m16n8k16.row.col.f32.bf16.bf16.f32 "
        "{%0,%1,%2,%3}, {%4,%5,%6,%7}, {%8,%9}, {%0,%1,%2,%3};"
        : "+f"(c[0]), "+f"(c[1]), "+f"(c[2]), "+f"(c[3])
        : "r"(a[0]), "r"(a[1]), "r"(a[2]), "r"(a[3]), "r"(b[0]), "r"(b[1]));
}

// ---------------------------------------------------------------------------
// Weight prep layers 0,1: Bt[256][128] hi/lo (proven R13)
// ---------------------------------------------------------------------------
__global__ void w_prep(const float* __restrict__ Wn, const float* __restrict__ Ws,
                       unsigned short* __restrict__ bh, unsigned short* __restrict__ bl) {
    int i = blockIdx.x * 256 + threadIdx.x;
    if (i >= 256 * 64) return;
    int n = i >> 6;
    int kp = (i & 63) * 2;
    float w0, w1;
    if (n < 128) { w0 = Wn[kp * 128 + n]; w1 = Wn[(kp + 1) * 128 + n]; }
    else         { w0 = Ws[kp * 128 + n - 128]; w1 = Ws[(kp + 1) * 128 + n - 128]; }
    __nv_bfloat16 h0 = __float2bfloat16(w0), h1 = __float2bfloat16(w1);
    *reinterpret_cast<unsigned*>(bh + n * 128 + kp) =
        (unsigned)__bfloat16_as_ushort(h0) | ((unsigned)__bfloat16_as_ushort(h1) << 16);
    *reinterpret_cast<unsigned*>(bl + n * 128 + kp) =
        pbf2(w0 - __bfloat162float(h0), w1 - __bfloat162float(h1));
}

// Weight prep layer 2: Bt[96][128] (rows 0..39 = Wn, 40..79 = Ws, 80..95 zero)
__global__ void w_prep3(const float* __restrict__ Wn, const float* __restrict__ Ws) {
    int i = blockIdx.x * 256 + threadIdx.x;
    if (i >= 96 * 64) return;
    int n = i >> 6;
    int kp = (i & 63) * 2;
    float w0 = 0.f, w1 = 0.f;
    if (n < 40)      { w0 = Wn[kp * 40 + n]; w1 = Wn[(kp + 1) * 40 + n]; }
    else if (n < 80) { w0 = Ws[kp * 40 + n - 40]; w1 = Ws[(kp + 1) * 40 + n - 40]; }
    __nv_bfloat16 h0 = __float2bfloat16(w0), h1 = __float2bfloat16(w1);
    *reinterpret_cast<unsigned*>(g_Bh3 + n * 128 + kp) =
        (unsigned)__bfloat16_as_ushort(h0) | ((unsigned)__bfloat16_as_ushort(h1) << 16);
    *reinterpret_cast<unsigned*>(g_Bl3 + n * 128 + kp) =
        pbf2(w0 - __bfloat162float(h0), w1 - __bfloat162float(h1));
}

// ---------------------------------------------------------------------------
// mma.sync GEMM 128->256 (proven R16): fused 3-term
// ---------------------------------------------------------------------------
#define BSTR 136
#define OFF_AHI 0
#define OFF_ALO 34816
#define OFF_BTH 69632
#define OFF_BTL 139264
#define SMEM_MMA 208896

__global__ void __launch_bounds__(512, 1)
gemm128_mma(const float* __restrict__ A,
            const unsigned short* __restrict__ Bhi,
            const unsigned short* __restrict__ Blo,
            float* __restrict__ out, int M) {
    extern __shared__ char smc[];
    unsigned short* Ahi = reinterpret_cast<unsigned short*>(smc + OFF_AHI);
    unsigned short* Alo = reinterpret_cast<unsigned short*>(smc + OFF_ALO);
    unsigned short* Bth = reinterpret_cast<unsigned short*>(smc + OFF_BTH);
    unsigned short* Btl = reinterpret_cast<unsigned short*>(smc + OFF_BTL);

    const int tid = threadIdx.x;
    const int lane = tid & 31;
    const int w = tid >> 5;
    const int row0 = blockIdx.x * 128;

    for (int i = tid; i < 128 * 32; i += 512) {
        int r = i >> 5;
        int g = i & 31;
        int gr = row0 + r;
        if (gr >= M) gr = M - 1;
        float4 a = *reinterpret_cast<const float4*>(A + (size_t)gr * 128 + g * 4);
        __nv_bfloat16 hx = __float2bfloat16(a.x), hy = __float2bfloat16(a.y);
        __nv_bfloat16 hz = __float2bfloat16(a.z), hw = __float2bfloat16(a.w);
        uint2 hi, lo;
        hi.x = (unsigned)__bfloat16_as_ushort(hx) | ((unsigned)__bfloat16_as_ushort(hy) << 16);
        hi.y = (unsigned)__bfloat16_as_ushort(hz) | ((unsigned)__bfloat16_as_ushort(hw) << 16);
        lo.x = pbf2(a.x - __bfloat162float(hx), a.y - __bfloat162float(hy));
        lo.y = pbf2(a.z - __bfloat162float(hz), a.w - __bfloat162float(hw));
        *reinterpret_cast<uint2*>(Ahi + r * BSTR + g * 4) = hi;
        *reinterpret_cast<uint2*>(Alo + r * BSTR + g * 4) = lo;
    }
    for (int i = tid; i < 256 * 32; i += 512) {
        int n = i >> 5;
        int g = i & 31;
        uint2 h = *reinterpret_cast<const uint2*>(Bhi + n * 128 + g * 4);
        uint2 l = *reinterpret_cast<const uint2*>(Blo + n * 128 + g * 4);
        *reinterpret_cast<uint2*>(Bth + n * BSTR + g * 4) = h;
        *reinterpret_cast<uint2*>(Btl + n * BSTR + g * 4) = l;
    }
    __syncthreads();

    const int wm = w & 3;
    const int wn = w >> 2;
    const int mat = lane >> 3;
    const int rim = lane & 7;

    float acc[2][8][4];
#pragma unroll
    for (int mt = 0; mt < 2; mt++)
#pragma unroll
        for (int nt = 0; nt < 8; nt++)
#pragma unroll
            for (int q = 0; q < 4; q++) acc[mt][nt][q] = 0.f;

    const int a_r_base = wm * 32 + (mat & 1) * 8 + rim;
    const int a_k_off = (mat >> 1) * 8;
    const int b_n_base = wn * 64 + (mat >> 1) * 8 + rim;
    const int b_k_off = (mat & 1) * 8;

#pragma unroll
    for (int ks = 0; ks < 8; ks++) {
        const int k0 = ks * 16;
        uint32_t ah[2][4], al[2][4];
#pragma unroll
        for (int mt = 0; mt < 2; mt++) {
            int ro = (a_r_base + mt * 16) * BSTR + k0 + a_k_off;
            ldsm_x4(ah[mt], smem_u32(Ahi + ro));
            ldsm_x4(al[mt], smem_u32(Alo + ro));
        }
#pragma unroll
        for (int np = 0; np < 4; np++) {
            uint32_t bh[4], bl[4];
            int no = (b_n_base + np * 16) * BSTR + k0 + b_k_off;
            ldsm_x4(bh, smem_u32(Bth + no));
            ldsm_x4(bl, smem_u32(Btl + no));
#pragma unroll
            for (int mt = 0; mt < 2; mt++) {
                float* c0 = acc[mt][2 * np];
                float* c1 = acc[mt][2 * np + 1];
                mma_bf16(c0, ah[mt], bh);
                mma_bf16(c1, ah[mt], bh + 2);
                mma_bf16(c0, al[mt], bh);
                mma_bf16(c1, al[mt], bh + 2);
                mma_bf16(c0, ah[mt], bl);
                mma_bf16(c1, ah[mt], bl + 2);
            }
        }
    }

    const int gid = lane >> 2;
    const int tig = lane & 3;
#pragma unroll
    for (int mt = 0; mt < 2; mt++) {
#pragma unroll
        for (int half = 0; half < 2; half++) {
            int r = row0 + wm * 32 + mt * 16 + half * 8 + gid;
            if (r < M) {
                float* o = out + (size_t)r * 256 + wn * 64 + tig * 2;
#pragma unroll
                for (int nt = 0; nt < 8; nt++) {
                    float2 v = make_float2(acc[mt][nt][2 * half], acc[mt][nt][2 * half + 1]);
                    *reinterpret_cast<float2*>(o + nt * 8) = v;
                }
            }
        }
    }
}

// ---------------------------------------------------------------------------
// mma.sync GEMM 128->80 (layer 3): BM=128, BN=96 (cols 80..95 discarded).
// 16 warps = 8 row-groups x 2 col-groups(48). mt=1, np=3. Fused 3-term.
// ---------------------------------------------------------------------------
#define OFF3_AHI 0
#define OFF3_ALO 34816
#define OFF3_BTH 69632
#define OFF3_BTL 95744
#define SMEM_MMA3 121856

__global__ void __launch_bounds__(512, 1)
gemm80_mma(const float* __restrict__ A,
           float* __restrict__ out, int M) {
    extern __shared__ char smc[];
    unsigned short* Ahi = reinterpret_cast<unsigned short*>(smc + OFF3_AHI);
    unsigned short* Alo = reinterpret_cast<unsigned short*>(smc + OFF3_ALO);
    unsigned short* Bth = reinterpret_cast<unsigned short*>(smc + OFF3_BTH);
    unsigned short* Btl = reinterpret_cast<unsigned short*>(smc + OFF3_BTL);

    const int tid = threadIdx.x;
    const int lane = tid & 31;
    const int w = tid >> 5;
    const int row0 = blockIdx.x * 128;

    for (int i = tid; i < 128 * 32; i += 512) {
        int r = i >> 5;
        int g = i & 31;
        int gr = row0 + r;
        if (gr >= M) gr = M - 1;
        float4 a = *reinterpret_cast<const float4*>(A + (size_t)gr * 128 + g * 4);
        __nv_bfloat16 hx = __float2bfloat16(a.x), hy = __float2bfloat16(a.y);
        __nv_bfloat16 hz = __float2bfloat16(a.z), hw = __float2bfloat16(a.w);
        uint2 hi, lo;
        hi.x = (unsigned)__bfloat16_as_ushort(hx) | ((unsigned)__bfloat16_as_ushort(hy) << 16);
        hi.y = (unsigned)__bfloat16_as_ushort(hz) | ((unsigned)__bfloat16_as_ushort(hw) << 16);
        lo.x = pbf2(a.x - __bfloat162float(hx), a.y - __bfloat162float(hy));
        lo.y = pbf2(a.z - __bfloat162float(hz), a.w - __bfloat162float(hw));
        *reinterpret_cast<uint2*>(Ahi + r * BSTR + g * 4) = hi;
        *reinterpret_cast<uint2*>(Alo + r * BSTR + g * 4) = lo;
    }
    for (int i = tid; i < 96 * 32; i += 512) {
        int n = i >> 5;
        int g = i & 31;
        uint2 h = *reinterpret_cast<const uint2*>(g_Bh3 + n * 128 + g * 4);
        uint2 l = *reinterpret_cast<const uint2*>(g_Bl3 + n * 128 + g * 4);
        *reinterpret_cast<uint2*>(Bth + n * BSTR + g * 4) = h;
        *reinterpret_cast<uint2*>(Btl + n * BSTR + g * 4) = l;
    }
    __syncthreads();

    const int wm = w & 7;        // 16-row group
    const int wn = w >> 3;       // 48-col group
    const int mat = lane >> 3;
    const int rim = lane & 7;

    float acc[6][4];
#pragma unroll
    for (int nt = 0; nt < 6; nt++)
#pragma unroll
        for (int q = 0; q < 4; q++) acc[nt][q] = 0.f;

    const int a_r_base = wm * 16 + (mat & 1) * 8 + rim;
    const int a_k_off = (mat >> 1) * 8;
    const int b_n_base = wn * 48 + (mat >> 1) * 8 + rim;
    const int b_k_off = (mat & 1) * 8;

#pragma unroll
    for (int ks = 0; ks < 8; ks++) {
        const int k0 = ks * 16;
        uint32_t ah[4], al[4];
        int ro = a_r_base * BSTR + k0 + a_k_off;
        ldsm_x4(ah, smem_u32(Ahi + ro));
        ldsm_x4(al, smem_u32(Alo + ro));
#pragma unroll
        for (int np = 0; np < 3; np++) {
            uint32_t bh[4], bl[4];
            int no = (b_n_base + np * 16) * BSTR + k0 + b_k_off;
            ldsm_x4(bh, smem_u32(Bth + no));
            ldsm_x4(bl, smem_u32(Btl + no));
            float* c0 = acc[2 * np];
            float* c1 = acc[2 * np + 1];
            mma_bf16(c0, ah, bh);
            mma_bf16(c1, ah, bh + 2);
            mma_bf16(c0, al, bh);
            mma_bf16(c1, al, bh + 2);
            mma_bf16(c0, ah, bl);
            mma_bf16(c1, ah, bl + 2);
        }
    }

    const int gid = lane >> 2;
    const int tig = lane & 3;
#pragma unroll
    for (int half = 0; half < 2; half++) {
        int r = row0 + wm * 16 + half * 8 + gid;
        if (r < M) {
            float* o = out + (size_t)r * 80;
#pragma unroll
            for (int nt = 0; nt < 6; nt++) {
                int col = wn * 48 + nt * 8 + tig * 2;
                if (col < 80) {
                    float2 v = make_float2(acc[nt][2 * half], acc[nt][2 * half + 1]);
                    *reinterpret_cast<float2*>(o + col) = v;
                }
            }
        }
    }
}

// ---------------------------------------------------------------------------
// CSR build — vectorized (proven R14)
// ---------------------------------------------------------------------------
__global__ void zero_i(int* p, int n) {
    int i = blockIdx.x * blockDim.x + threadIdx.x;
    if (i < n) p[i] = 0;
}
__global__ void count_deg4(const int* __restrict__ dst, int E) {
    int i = blockIdx.x * blockDim.x + threadIdx.x;
    int e0 = i * 4;
    if (e0 + 3 < E) {
        int4 d = *reinterpret_cast<const int4*>(dst + e0);
        atomicAdd(&g_degi[d.x], 1);
        atomicAdd(&g_degi[d.y], 1);
        atomicAdd(&g_degi[d.z], 1);
        atomicAdd(&g_degi[d.w], 1);
    } else {
        for (int e = e0; e < E; ++e) atomicAdd(&g_degi[dst[e]], 1);
    }
}
__global__ void scan_block(const int* __restrict__ in, int* __restrict__ out,
                           int* bsum, int n) {
    int i = blockIdx.x * 256 + threadIdx.x;
    int lane = threadIdx.x & 31, w = threadIdx.x >> 5;
    int v = (i < n) ? in[i] : 0;
    int incl = v;
#pragma unroll
    for (int d = 1; d < 32; d <<= 1) {
        int t = __shfl_up_sync(0xffffffffu, incl, d);
        if (lane >= d) incl += t;
    }
    __shared__ int ws[8];
    if (lane == 31) ws[w] = incl;
    __syncthreads();
    if (threadIdx.x < 8) {
        int x = ws[threadIdx.x];
        int in2 = x;
#pragma unroll
        for (int d = 1; d < 8; d <<= 1) {
            int t = __shfl_up_sync(0xffu, in2, d);
            if (threadIdx.x >= (unsigned)d) in2 += t;
        }
        ws[threadIdx.x] = in2 - x;
        if (threadIdx.x == 7 && bsum) bsum[blockIdx.x] = in2;
    }
    __syncthreads();
    if (i < n) out[i] = ws[w] + incl - v;
}
__global__ void add_off(int M, int E) {
    int i = blockIdx.x * blockDim.x + threadIdx.x;
    if (i < M) {
        int o = g_off[i] + g_bsum[i >> 8];
        g_off[i] = o;
        g_cur[i] = o;
        g_rdeg[i] = 1.0f / fmaxf((float)g_degi[i], 1.0f);
    } else if (i == M) {
        g_off[M] = E;
    }
}
__global__ void scatter_edges4(const int* __restrict__ src,
                               const int* __restrict__ dst, int E) {
    int i = blockIdx.x * blockDim.x + threadIdx.x;
    int e0 = i * 4;
    if (e0 + 3 < E) {
        int4 d = *reinterpret_cast<const int4*>(dst + e0);
        int4 s = *reinterpret_cast<const int4*>(src + e0);
        g_esrc[atomicAdd(&g_cur[d.x], 1)] = s.x;
        g_esrc[atomicAdd(&g_cur[d.y], 1)] = s.y;
        g_esrc[atomicAdd(&g_cur[d.z], 1)] = s.z;
        g_esrc[atomicAdd(&g_cur[d.w], 1)] = s.w;
    } else {
        for (int e = e0; e < E; ++e)
            g_esrc[atomicAdd(&g_cur[dst[e]], 1)] = src[e];
    }
}

// ---------------------------------------------------------------------------
// Fused CSR aggregate + combine — 8-way MLP (proven R14)
// ---------------------------------------------------------------------------
#define ACC4(d, v) { d.x += v.x; d.y += v.y; d.z += v.z; d.w += v.w; }

template <bool RELU>
__global__ void aggcomb128(const float* __restrict__ TS,
                           const float* __restrict__ b,
                           float* __restrict__ out, int M) {
    int n = blockIdx.x * 8 + (threadIdx.x >> 5);
    if (n >= M) return;
    int lane = threadIdx.x & 31;
    int beg = g_off[n], end = g_off[n + 1];

    float4 a0 = make_float4(0.f, 0.f, 0.f, 0.f);
    float4 a1 = make_float4(0.f, 0.f, 0.f, 0.f);
    float4 a2 = make_float4(0.f, 0.f, 0.f, 0.f);
    float4 a3 = make_float4(0.f, 0.f, 0.f, 0.f);

    for (int j0 = beg; j0 < end; j0 += 32) {
        int cnt = min(32, end - j0);
        int s = (lane < cnt) ? g_esrc[j0 + lane] : 0;
        int t = 0;
        for (; t + 7 < cnt; t += 8) {
            int s0 = __shfl_sync(0xffffffffu, s, t);
            int s1 = __shfl_sync(0xffffffffu, s, t + 1);
            int s2 = __shfl_sync(0xffffffffu, s, t + 2);
            int s3 = __shfl_sync(0xffffffffu, s, t + 3);
            int s4 = __shfl_sync(0xffffffffu, s, t + 4);
            int s5 = __shfl_sync(0xffffffffu, s, t + 5);
            int s6 = __shfl_sync(0xffffffffu, s, t + 6);
            int s7 = __shfl_sync(0xffffffffu, s, t + 7);
            float4 v0 = *reinterpret_cast<const float4*>(TS + (size_t)s0 * 256 + lane * 4);
            float4 v1 = *reinterpret_cast<const float4*>(TS + (size_t)s1 * 256 + lane * 4);
            float4 v2 = *reinterpret_cast<const float4*>(TS + (size_t)s2 * 256 + lane * 4);
            float4 v3 = *reinterpret_cast<const float4*>(TS + (size_t)s3 * 256 + lane * 4);
            float4 v4 = *reinterpret_cast<const float4*>(TS + (size_t)s4 * 256 + lane * 4);
            float4 v5 = *reinterpret_cast<const float4*>(TS + (size_t)s5 * 256 + lane * 4);
            float4 v6 = *reinterpret_cast<const float4*>(TS + (size_t)s6 * 256 + lane * 4);
            float4 v7 = *reinterpret_cast<const float4*>(TS + (size_t)s7 * 256 + lane * 4);
            ACC4(a0, v0) ACC4(a1, v1) ACC4(a2, v2) ACC4(a3, v3)
            ACC4(a0, v4) ACC4(a1, v5) ACC4(a2, v6) ACC4(a3, v7)
        }
        for (; t + 3 < cnt; t += 4) {
            int s0 = __shfl_sync(0xffffffffu, s, t);
            int s1 = __shfl_sync(0xffffffffu, s, t + 1);
            int s2 = __shfl_sync(0xffffffffu, s, t + 2);
            int s3 = __shfl_sync(0xffffffffu, s, t + 3);
            float4 v0 = *reinterpret_cast<const float4*>(TS + (size_t)s0 * 256 + lane * 4);
            float4 v1 = *reinterpret_cast<const float4*>(TS + (size_t)s1 * 256 + lane * 4);
            float4 v2 = *reinterpret_cast<const float4*>(TS + (size_t)s2 * 256 + lane * 4);
            float4 v3 = *reinterpret_cast<const float4*>(TS + (size_t)s3 * 256 + lane * 4);
            ACC4(a0, v0) ACC4(a1, v1) ACC4(a2, v2) ACC4(a3, v3)
        }
        for (; t < cnt; ++t) {
            int s0 = __shfl_sync(0xffffffffu, s, t);
            float4 v0 = *reinterpret_cast<const float4*>(TS + (size_t)s0 * 256 + lane * 4);
            ACC4(a0, v0)
        }
    }
    float r = g_rdeg[n];
    float4 sf = *reinterpret_cast<const float4*>(TS + (size_t)n * 256 + 128 + lane * 4);
    float4 bb = *reinterpret_cast<const float4*>(b + lane * 4);
    float4 v;
    v.x = sf.x + (a0.x + a1.x + a2.x + a3.x) * r + bb.x;
    v.y = sf.y + (a0.y + a1.y + a2.y + a3.y) * r + bb.y;
    v.z = sf.z + (a0.z + a1.z + a2.z + a3.z) * r + bb.z;
    v.w = sf.w + (a0.w + a1.w + a2.w + a3.w) * r + bb.w;
    if (RELU) {
        v.x = fmaxf(v.x, 0.f); v.y = fmaxf(v.y, 0.f);
        v.z = fmaxf(v.z, 0.f); v.w = fmaxf(v.w, 0.f);
    }
    *reinterpret_cast<float4*>(out + (size_t)n * 128 + lane * 4) = v;
}

__global__ void aggcomb40(const float* __restrict__ TS,
                          const float* __restrict__ b,
                          float* __restrict__ out, int M) {
    int n = blockIdx.x * 8 + (threadIdx.x >> 5);
    if (n >= M) return;
    int lane = threadIdx.x & 31;
    int beg = g_off[n], end = g_off[n + 1];
    bool act = lane < 10;
    int laneo = act ? lane : 0;

    float4 a0 = make_float4(0.f, 0.f, 0.f, 0.f);
    float4 a1 = make_float4(0.f, 0.f, 0.f, 0.f);
    float4 a2 = make_float4(0.f, 0.f, 0.f, 0.f);
    float4 a3 = make_float4(0.f, 0.f, 0.f, 0.f);

    for (int j0 = beg; j0 < end; j0 += 32) {
        int cnt = min(32, end - j0);
        int s = (lane < cnt) ? g_esrc[j0 + lane] : 0;
        int t = 0;
        for (; t + 7 < cnt; t += 8) {
            int s0 = __shfl_sync(0xffffffffu, s, t);
            int s1 = __shfl_sync(0xffffffffu, s, t + 1);
            int s2 = __shfl_sync(0xffffffffu, s, t + 2);
            int s3 = __shfl_sync(0xffffffffu, s, t + 3);
            int s4 = __shfl_sync(0xffffffffu, s, t + 4);
            int s5 = __shfl_sync(0xffffffffu, s, t + 5);
            int s6 = __shfl_sync(0xffffffffu, s, t + 6);
            int s7 = __shfl_sync(0xffffffffu, s, t + 7);
            float4 v0 = *reinterpret_cast<const float4*>(TS + (size_t)s0 * 80 + laneo * 4);
            float4 v1 = *reinterpret_cast<const float4*>(TS + (size_t)s1 * 80 + laneo * 4);
            float4 v2 = *reinterpret_cast<const float4*>(TS + (size_t)s2 * 80 + laneo * 4);
            float4 v3 = *reinterpret_cast<const float4*>(TS + (size_t)s3 * 80 + laneo * 4);
            float4 v4 = *reinterpret_cast<const float4*>(TS + (size_t)s4 * 80 + laneo * 4);
            float4 v5 = *reinterpret_cast<const float4*>(TS + (size_t)s5 * 80 + laneo * 4);
            float4 v6 = *reinterpret_cast<const float4*>(TS + (size_t)s6 * 80 + laneo * 4);
            float4 v7 = *reinterpret_cast<const float4*>(TS + (size_t)s7 * 80 + laneo * 4);
            ACC4(a0, v0) ACC4(a1, v1) ACC4(a2, v2) ACC4(a3, v3)
            ACC4(a0, v4) ACC4(a1, v5) ACC4(a2, v6) ACC4(a3, v7)
        }
        for (; t + 3 < cnt; t += 4) {
            int s0 = __shfl_sync(0xffffffffu, s, t);
            int s1 = __shfl_sync(0xffffffffu, s, t + 1);
            int s2 = __shfl_sync(0xffffffffu, s, t + 2);
            int s3 = __shfl_sync(0xffffffffu, s, t + 3);
            float4 v0 = *reinterpret_cast<const float4*>(TS + (size_t)s0 * 80 + laneo * 4);
            float4 v1 = *reinterpret_cast<const float4*>(TS + (size_t)s1 * 80 + laneo * 4);
            float4 v2 = *reinterpret_cast<const float4*>(TS + (size_t)s2 * 80 + laneo * 4);
            float4 v3 = *reinterpret_cast<const float4*>(TS + (size_t)s3 * 80 + laneo * 4);
            ACC4(a0, v0) ACC4(a1, v1) ACC4(a2, v2) ACC4(a3, v3)
        }
        for (; t < cnt; ++t) {
            int s0 = __shfl_sync(0xffffffffu, s, t);
            float4 v0 = *reinterpret_cast<const float4*>(TS + (size_t)s0 * 80 + laneo * 4);
            ACC4(a0, v0)
        }
    }
    if (act) {
        float r = g_rdeg[n];
        float4 sf = *reinterpret_cast<const float4*>(TS + (size_t)n * 80 + 40 + lane * 4);
        float4 bb = *reinterpret_cast<const float4*>(b + lane * 4);
        float4 v;
        v.x = sf.x + (a0.x + a1.x + a2.x + a3.x) * r + bb.x;
        v.y = sf.y + (a0.y + a1.y + a2.y + a3.y) * r + bb.y;
        v.z = sf.z + (a0.z + a1.z + a2.z + a3.z) * r + bb.z;
        v.w = sf.w + (a0.w + a1.w + a2.w + a3.w) * r + bb.w;
        *reinterpret_cast<float4*>(out + (size_t)n * 40 + lane * 4) = v;
    }
}

// ---------------------------------------------------------------------------
// launch
// ---------------------------------------------------------------------------
static inline int cdiv(int a, int b) { return (a + b - 1) / b; }

extern "C" void kernel_launch(void* const* d_in, const int* in_sizes, int n_in,
                              void* d_out, int out_size) {
    const float* feat = (const float*)d_in[0];
    const int*   src  = (const int*)d_in[1];
    const int*   dst  = (const int*)d_in[2];
    const float* wS0 = (const float*)d_in[3];
    const float* wN0 = (const float*)d_in[4];
    const float* b0  = (const float*)d_in[5];
    const float* wS1 = (const float*)d_in[6];
    const float* wN1 = (const float*)d_in[7];
    const float* b1  = (const float*)d_in[8];
    const float* wS2 = (const float*)d_in[9];
    const float* wN2 = (const float*)d_in[10];
    const float* b2  = (const float*)d_in[11];
    float* out = (float*)d_out;

    const int M = in_sizes[0] / 128;
    const int E = in_sizes[1];

    void *pTS, *pH, *pDegi, *pOff, *pBsum, *pBh, *pBl;
    cudaGetSymbolAddress(&pTS, g_TS);
    cudaGetSymbolAddress(&pH, g_H);
    cudaGetSymbolAddress(&pDegi, g_degi);
    cudaGetSymbolAddress(&pOff, g_off);
    cudaGetSymbolAddress(&pBsum, g_bsum);
    cudaGetSymbolAddress(&pBh, g_Bh);
    cudaGetSymbolAddress(&pBl, g_Bl);
    float* TS = (float*)pTS;
    float* H = (float*)pH;
    int* degi = (int*)pDegi;
    int* off = (int*)pOff;
    int* bsum = (int*)pBsum;
    unsigned short* Bh = (unsigned short*)pBh;
    unsigned short* Bl = (unsigned short*)pBl;

    static bool attr_done = false;
    if (!attr_done) {
        cudaFuncSetAttribute((const void*)gemm128_mma,
                             cudaFuncAttributeMaxDynamicSharedMemorySize, SMEM_MMA);
        cudaFuncSetAttribute((const void*)gemm80_mma,
                             cudaFuncAttributeMaxDynamicSharedMemorySize, SMEM_MMA3);
        attr_done = true;
    }

    const int gemm_blocks = cdiv(M, 128);
    const int nscan = cdiv(M, 256);
    const int node_blocks = cdiv(M, 8);
    const int e4_blocks = cdiv(cdiv(E, 4), 256);

    // launch #4 = gemm128_mma (profiler captures it)
    w_prep<<<64, 256>>>(wN0, wS0, Bh + 0 * 32768, Bl + 0 * 32768);    // 1
    w_prep<<<64, 256>>>(wN1, wS1, Bh + 1 * 32768, Bl + 1 * 32768);    // 2
    zero_i<<<cdiv(M, 256), 256>>>(degi, M);                           // 3
    gemm128_mma<<<gemm_blocks, 512, SMEM_MMA>>>(feat, Bh, Bl, TS, M); // 4 (layer1)

    // CSR build + layer-3 weight prep (independent of TS)
    w_prep3<<<24, 256>>>(wN2, wS2);                                   // 5
    count_deg4<<<e4_blocks, 256>>>(dst, E);                           // 6
    scan_block<<<nscan, 256>>>(degi, off, bsum, M);                   // 7
    scan_block<<<1, 256>>>(bsum, bsum, nullptr, nscan);               // 8
    add_off<<<cdiv(M + 1, 256), 256>>>(M, E);                         // 9
    scatter_edges4<<<e4_blocks, 256>>>(src, dst, E);                  // 10

    // layer 1 aggregate
    aggcomb128<true><<<node_blocks, 256>>>(TS, b0, H, M);

    // layer 2
    gemm128_mma<<<gemm_blocks, 512, SMEM_MMA>>>(H, Bh + 32768, Bl + 32768, TS, M);
    aggcomb128<true><<<node_blocks, 256>>>(TS, b1, H, M);

    // layer 3 (mma, 80-wide)
    gemm80_mma<<<gemm_blocks, 512, SMEM_MMA3>>>(H, TS, M);
    aggcomb40<<<node_blocks, 256>>>(TS, b2, out, M);
}